// round 17
// baseline (speedup 1.0000x reference)
#include <cuda_runtime.h>
#include <cstdint>

#define BB      1024
#define MAXLEN  200
#define FF      64
#define DD      64
#define NT      256
#define KT      (MAXLEN * DD)              // 12800 floats per k tile
#define NCHUNK  4
#define CH      50                         // rows per chunk CTA

__device__ float g_u[BB * DD];             // u per batch
__device__ float g_wacc[BB * DD];          // partial weighted sums
__device__ float g_esum[BB];               // partial exp sums

__device__ __forceinline__ float fast_sigmoid(float x) {
    float t;
    asm("tanh.approx.f32 %0, %1;" : "=f"(t) : "f"(0.5f * x));
    return fmaf(0.5f, t, 0.5f);
}
__device__ __forceinline__ float fast_exp8(float x) {   // exp(x/8)
    float e;
    asm("ex2.approx.f32 %0, %1;" : "=f"(e) : "f"(x * 0.18033688011112042f));
    return e;
}

// ========== Kernel 1: u[b] = ((fs.q[b]) @ Wq) @ Wk^T ; zero accumulators ==========
__global__ __launch_bounds__(NT, 8)
void u_kernel(const float* __restrict__ q,
              const float* __restrict__ fs,
              const float* __restrict__ Wq,
              const float* __restrict__ Wk) {
    __shared__ float spart[16 * DD];
    __shared__ float squ[DD];
    __shared__ float stmp[DD];

    const int b   = blockIdx.x;
    const int tid = threadIdx.x;
    const int hw  = tid >> 4;
    const int l16 = tid & 15;

    // zero this batch's accumulators (runs before score kernel launches)
    if (tid < DD) g_wacc[b * DD + tid] = 0.f;
    if (tid == DD) g_esum[b] = 0.f;

    // qbar[d] = sum_f fs[f] * q[b,f,d]
    {
        const float4* qb4 = (const float4*)(q + (size_t)b * FF * DD);
        float4 a = make_float4(0.f, 0.f, 0.f, 0.f);
#pragma unroll
        for (int fi = 0; fi < 4; ++fi) {
            int f = hw + 16 * fi;
            float s = fs[f];
            float4 v = qb4[f * 16 + l16];
            a.x += s * v.x; a.y += s * v.y; a.z += s * v.z; a.w += s * v.w;
        }
        ((float4*)spart)[hw * 16 + l16] = a;
    }
    __syncthreads();
    if (tid < DD) {
        float s = 0.f;
#pragma unroll
        for (int i = 0; i < 16; ++i) s += spart[i * DD + tid];
        squ[tid] = s;
    }
    __syncthreads();

    // tmp[e] = sum_c qbar[c] * Wq[c,e]
    {
        float4 a = make_float4(0.f, 0.f, 0.f, 0.f);
#pragma unroll
        for (int ci = 0; ci < 4; ++ci) {
            int c = hw * 4 + ci;
            float s = squ[c];
            float4 v = ((const float4*)Wq)[c * 16 + l16];
            a.x += s * v.x; a.y += s * v.y; a.z += s * v.z; a.w += s * v.w;
        }
        ((float4*)spart)[hw * 16 + l16] = a;
    }
    __syncthreads();
    if (tid < DD) {
        float s = 0.f;
#pragma unroll
        for (int i = 0; i < 16; ++i) s += spart[i * DD + tid];
        stmp[tid] = s;
    }
    __syncthreads();

    // u[row] = sum_e tmp[e] * Wk[row,e]
    {
        float4 tv = ((const float4*)stmp)[l16];
#pragma unroll
        for (int r = 0; r < 4; ++r) {
            int row = hw + 16 * r;
            float4 wv = ((const float4*)(Wk + row * DD))[l16];
            float p = wv.x * tv.x + wv.y * tv.y + wv.z * tv.z + wv.w * tv.w;
#pragma unroll
            for (int o = 8; o; o >>= 1)
                p += __shfl_xor_sync(0xffffffffu, p, o);
            if (l16 == 0) g_u[b * DD + row] = p;
        }
    }
}

// ========== Kernel 2: 4 CTAs per batch, 12.8 KB each — small-stream k read ==========
__global__ __launch_bounds__(NT, 8)
void score_kernel(const float* __restrict__ k,
                  const int*   __restrict__ kes_length,
                  const float* __restrict__ bias) {
    __shared__ float spart[16 * DD];
    __shared__ float su[DD];
    __shared__ float sub[DD];
    __shared__ float swr[16];

    const int bid   = blockIdx.x;
    const int b     = bid >> 2;
    const int chunk = bid & 3;
    const int tid   = threadIdx.x;
    const int hw    = tid >> 4;            // half-warp id 0..15
    const int l16   = tid & 15;

    if (tid < 16)
        ((float4*)sub)[tid] = ((const float4*)(g_u + (size_t)b * DD))[tid];
    const int   len   = kes_length[b];
    const float biasD = bias[0] * (float)DD;
    const float mfill = (len == 0) ? 1.f : 0.f;
    __syncthreads();

    const float4  uv  = ((const float4*)sub)[l16];
    const int     t0  = chunk * CH;
    const float4* kb4 = (const float4*)(k + (size_t)b * KT + (size_t)t0 * DD);

    // fused: load -> dot -> 16-lane reduce -> exp -> accumulate (rows t0..t0+49)
    float4 wa   = make_float4(0.f, 0.f, 0.f, 0.f);
    float  esum = 0.f;
#pragma unroll
    for (int i = 0; i < 4; ++i) {
        int rl = hw + (i << 4);            // 0..63 ; valid < 50
        if (rl < CH) {
            float4 kv = kb4[rl * 16 + l16];
            float p = kv.x * uv.x + kv.y * uv.y + kv.z * uv.z + kv.w * uv.w;
#pragma unroll
            for (int o = 8; o; o >>= 1)
                p += __shfl_xor_sync(0xffffffffu, p, o);
            int   t = t0 + rl;
            float e = (t < len) ? fast_exp8(fast_sigmoid(p + biasD)) : mfill;
            wa.x += e * kv.x; wa.y += e * kv.y;
            wa.z += e * kv.z; wa.w += e * kv.w;
            esum += e;
        }
    }

    ((float4*)spart)[hw * 16 + l16] = wa;
    if (l16 == 0) swr[hw] = esum;
    __syncthreads();

    if (tid < DD) {
        float s = 0.f;
#pragma unroll
        for (int i = 0; i < 16; ++i) s += spart[i * DD + tid];
        atomicAdd(&g_wacc[b * DD + tid], s);     // REDG, spread addresses
    }
    if (tid == DD) {
        float tot = 0.f;
#pragma unroll
        for (int i = 0; i < 16; ++i) tot += swr[i];
        atomicAdd(&g_esum[b], tot);
    }
}

// ========== Kernel 3: out[b,e] = (wacc[b] @ Wv)[e] / esum[b] ==========
__global__ __launch_bounds__(64, 16)
void finish_kernel(const float* __restrict__ Wv,
                   float*       __restrict__ out) {
    __shared__ float sw[DD];
    const int b   = blockIdx.x;
    const int tid = threadIdx.x;           // e index, 0..63

    if (tid < 16)
        ((float4*)sw)[tid] = ((const float4*)(g_wacc + (size_t)b * DD))[tid];
    __syncthreads();

    float s = 0.f;
#pragma unroll
    for (int c = 0; c < DD; ++c)
        s += sw[c] * Wv[c * DD + tid];     // coalesced across tid
    out[(size_t)b * DD + tid] = s * (1.f / g_esum[b]);
}

extern "C" void kernel_launch(void* const* d_in, const int* in_sizes, int n_in,
                              void* d_out, int out_size) {
    const float* q    = (const float*)d_in[0];
    const float* k    = (const float*)d_in[1];
    // d_in[2] = v : unused by the reference computation
    const int*   kes  = (const int*)  d_in[3];
    const float* fs   = (const float*)d_in[4];
    const float* bias = (const float*)d_in[5];
    const float* Wq   = (const float*)d_in[6];
    const float* Wk   = (const float*)d_in[7];
    const float* Wv   = (const float*)d_in[8];
    float*       out  = (float*)d_out;

    u_kernel<<<BB, NT>>>(q, fs, Wq, Wk);
    score_kernel<<<BB * NCHUNK, NT>>>(k, kes, bias);
    finish_kernel<<<BB, 64>>>(Wv, out);
}